// round 2
// baseline (speedup 1.0000x reference)
#include <cuda_runtime.h>
#include <math.h>

// Problem constants: B=4, N=16, K=16, H=64, O=1
#define ZB 4
#define NN 16
#define NK 16
#define NH 64

// Scratch (allocation-free rule: __device__ globals)
// P[z][i][j][k][c] : basis tensor, 4*16*16*16*3 floats = 192 KB (L2-resident)
__device__ float g_P[ZB * NN * NN * NK * 3];
// h[z][a][h] accumulator: 4*16*64 = 4096 floats
__device__ float g_h[ZB * NN * NH];

// ---------------------------------------------------------------------------
// Kernel 1: compute basis P and zero the h accumulator.
// P[z,i,j,k,c] = cutoff(norm) * exp(-beta*(exp(-norm)-mean_k)^2) * diff_c / norm_sq
// ---------------------------------------------------------------------------
__global__ void k1_basis(const float* __restrict__ x) {
    int tid = blockIdx.x * blockDim.x + threadIdx.x;

    if (tid < ZB * NN * NH) g_h[tid] = 0.0f;

    if (tid >= ZB * NN * NN * NK) return;

    int k = tid & 15;
    int j = (tid >> 4) & 15;
    int i = (tid >> 8) & 15;
    int z = tid >> 12;

    const float* xi = x + (z * NN + i) * 3;
    const float* xj = x + (z * NN + j) * 3;
    float d0 = xi[0] - xj[0];
    float d1 = xi[1] - xj[1];
    float d2 = xi[2] - xj[2];

    float ns = d0 * d0 + d1 * d1 + d2 * d2 + 1e-5f;  // norm_sq + EPSILON
    float norm = sqrtf(ns);

    const float start = expf(-5.0f);                 // exp(-CUT_HI+CUT_LO), const-folded
    float mean = start + (float)k * (1.0f - start) * (1.0f / 15.0f);
    float bden = 0.125f * (1.0f - start);            // 2/K*(1-start)
    float beta = 1.0f / (bden * bden);

    float cutoff = (norm < 5.0f)
                 ? 0.5f * (cospif(norm * 0.2f) + 1.0f)   // cos(pi*norm/5)
                 : 0.0f;
    float e = expf(-norm);                           // alpha = 1, CUT_LO = 0
    float dd = e - mean;
    float smear = cutoff * expf(-beta * dd * dd);

    float s_over = smear / ns;                       // smear * (diff / norm_sq)

    int base = tid * 3;                              // [z][i][j][k] layout matches tid
    g_P[base + 0] = s_over * d0;
    g_P[base + 1] = s_over * d1;
    g_P[base + 2] = s_over * d2;
}

// ---------------------------------------------------------------------------
// Kernel 2: stream W once. One block per (a,b,d,e-half) -> contiguous 32 KB
// slice of W over (e_local,k,h). coef[j=e_local*16+k][z] =
// dot_c(P[z,a,b,k,:], P[z,d,e,k,:]) built in shared, then
// h[z,a,h] += coef * W streamed with LDG.128 evict-first.
// ---------------------------------------------------------------------------
__global__ void __launch_bounds__(256) k2_main(const float* __restrict__ W) {
    __shared__ float4 scoef[128];          // [j_local] -> (z0,z1,z2,z3)
    __shared__ float  sred[8 * 256];       // [warp][z*64+h]  (8 KB)

    int blk = blockIdx.x;                  // a*512 + b*32 + d*2 + eh
    int eh = blk & 1;
    int d  = (blk >> 1) & 15;
    int b  = (blk >> 5) & 15;
    int a  = blk >> 9;

    int t = threadIdx.x;

    // --- coefficient table: threads 0..127 compute j_local = t ---
    if (t < 128) {
        int e_local = t >> 4;
        int k = t & 15;
        int e = (eh << 3) + e_local;
        float cf[4];
#pragma unroll
        for (int z = 0; z < 4; z++) {
            const float* p1 = &g_P[((((z * NN + a) * NN + b) * NK) + k) * 3];
            const float* p2 = &g_P[((((z * NN + d) * NN + e) * NK) + k) * 3];
            cf[z] = p1[0] * p2[0] + p1[1] * p2[1] + p1[2] * p2[2];
        }
        scoef[t] = make_float4(cf[0], cf[1], cf[2], cf[3]);
    }
    __syncthreads();

    // --- main streaming loop: 8 iterations over 32 KB contiguous slice ---
    int h4 = t & 15;                       // which float4 of the 64 h values
    int g  = t >> 4;                       // group 0..15 over j_local rows
    // slice base: ((a,b,d) slice of 4096 float4 rows) + eh*2048 float4
    const float4* Wb = (const float4*)W + ((size_t)(blk >> 1) << 12) + ((size_t)eh << 11);

    float acc0x = 0.f, acc0y = 0.f, acc0z = 0.f, acc0w = 0.f;
    float acc1x = 0.f, acc1y = 0.f, acc1z = 0.f, acc1w = 0.f;
    float acc2x = 0.f, acc2y = 0.f, acc2z = 0.f, acc2w = 0.f;
    float acc3x = 0.f, acc3y = 0.f, acc3z = 0.f, acc3w = 0.f;

#pragma unroll
    for (int it = 0; it < 8; it++) {
        int j = g + (it << 4);             // j_local 0..127; warp reads 512B contiguous
        float4 w = __ldcs(&Wb[j * 16 + h4]);
        float4 cf = scoef[j];
        acc0x += cf.x * w.x; acc0y += cf.x * w.y; acc0z += cf.x * w.z; acc0w += cf.x * w.w;
        acc1x += cf.y * w.x; acc1y += cf.y * w.y; acc1z += cf.y * w.z; acc1w += cf.y * w.w;
        acc2x += cf.z * w.x; acc2y += cf.z * w.y; acc2z += cf.z * w.z; acc2w += cf.z * w.w;
        acc3x += cf.w * w.x; acc3y += cf.w * w.y; acc3z += cf.w * w.z; acc3w += cf.w * w.w;
    }

    // --- warp-level pre-reduction: combine g pairs (t and t^16 share h4) ---
#define SHFL_ADD(v) v += __shfl_xor_sync(0xFFFFFFFFu, v, 16)
    SHFL_ADD(acc0x); SHFL_ADD(acc0y); SHFL_ADD(acc0z); SHFL_ADD(acc0w);
    SHFL_ADD(acc1x); SHFL_ADD(acc1y); SHFL_ADD(acc1z); SHFL_ADD(acc1w);
    SHFL_ADD(acc2x); SHFL_ADD(acc2y); SHFL_ADD(acc2z); SHFL_ADD(acc2w);
    SHFL_ADD(acc3x); SHFL_ADD(acc3y); SHFL_ADD(acc3z); SHFL_ADD(acc3w);
#undef SHFL_ADD

    // lanes 0..15 of each warp store their combined partials: [warp][z][h4 float4]
    int lane = t & 31;
    int wrp  = t >> 5;                     // 0..7
    if (lane < 16) {
        float4* r4 = (float4*)sred;        // [warp][z][h4] of float4 -> [8][4][16]
        int base = (wrp * 4) * 16 + h4;
        r4[base + 0 * 16] = make_float4(acc0x, acc0y, acc0z, acc0w);
        r4[base + 1 * 16] = make_float4(acc1x, acc1y, acc1z, acc1w);
        r4[base + 2 * 16] = make_float4(acc2x, acc2y, acc2z, acc2w);
        r4[base + 3 * 16] = make_float4(acc3x, acc3y, acc3z, acc3w);
    }
    __syncthreads();

    // thread t owns (z = t>>6, h = t&63); sum across 8 warps, one atomic.
    float s = 0.0f;
#pragma unroll
    for (int w2 = 0; w2 < 8; w2++) s += sred[w2 * 256 + t];

    int z = t >> 6;
    int h = t & 63;
    atomicAdd(&g_h[(z * NN + a) * NH + h], s);
}

// ---------------------------------------------------------------------------
// Kernel 3: out[z,a] = silu(h[z,a,:]) . w_fc + b_fc
// ---------------------------------------------------------------------------
__global__ void k3_head(const float* __restrict__ w_fc,
                        const float* __restrict__ b_fc,
                        float* __restrict__ out) {
    int t = threadIdx.x;                   // 0..63 = z*16+a
    if (t >= ZB * NN) return;
    const float* hp = &g_h[t * NH];
    float acc = 0.0f;
#pragma unroll
    for (int h = 0; h < NH; h++) {
        float v = hp[h];
        float s = v / (1.0f + expf(-v));
        acc += s * w_fc[h];
    }
    out[t] = acc + b_fc[0];
}

// ---------------------------------------------------------------------------
extern "C" void kernel_launch(void* const* d_in, const int* in_sizes, int n_in,
                              void* d_out, int out_size) {
    const float* x   = nullptr;
    const float* W   = nullptr;
    const float* wfc = nullptr;
    const float* bfc = nullptr;
    for (int i = 0; i < n_in; i++) {
        long long s = in_sizes[i];
        if      (s == (long long)ZB * NN * 3)                 x   = (const float*)d_in[i];
        else if (s == (long long)NN * NN * NN * NN * NK * NH) W   = (const float*)d_in[i];
        else if (s == NH)                                     wfc = (const float*)d_in[i];
        else if (s == 1)                                      bfc = (const float*)d_in[i];
    }

    k1_basis<<<64, 256>>>(x);
    k2_main<<<NN * NN * NN * 2, 256>>>(W);   // 8192 blocks, 32 KB each
    k3_head<<<1, 64>>>(wfc, bfc, (float*)d_out);
}

// round 3
// speedup vs baseline: 1.0981x; 1.0981x over previous
#include <cuda_runtime.h>
#include <math.h>

// Problem constants: B=4, N=16, K=16, H=64, O=1
#define ZB 4
#define NN 16
#define NK 16
#define NH 64

// Scratch (allocation-free rule: __device__ globals)
__device__ float g_P[ZB * NN * NN * NK * 3];   // basis, 192 KB (L2-resident)
__device__ float g_h[ZB * NN * NH];            // h accumulator, 16 KB

// ---------------------------------------------------------------------------
// Kernel 1: compute basis P and zero the h accumulator.
// ---------------------------------------------------------------------------
__global__ void k1_basis(const float* __restrict__ x) {
    int tid = blockIdx.x * blockDim.x + threadIdx.x;

    if (tid < ZB * NN * NH) g_h[tid] = 0.0f;

    if (tid >= ZB * NN * NN * NK) return;

    int k = tid & 15;
    int j = (tid >> 4) & 15;
    int i = (tid >> 8) & 15;
    int z = tid >> 12;

    const float* xi = x + (z * NN + i) * 3;
    const float* xj = x + (z * NN + j) * 3;
    float d0 = xi[0] - xj[0];
    float d1 = xi[1] - xj[1];
    float d2 = xi[2] - xj[2];

    float ns = d0 * d0 + d1 * d1 + d2 * d2 + 1e-5f;
    float norm = sqrtf(ns);

    const float start = expf(-5.0f);
    float mean = start + (float)k * (1.0f - start) * (1.0f / 15.0f);
    float bden = 0.125f * (1.0f - start);
    float beta = 1.0f / (bden * bden);

    float cutoff = (norm < 5.0f)
                 ? 0.5f * (cospif(norm * 0.2f) + 1.0f)
                 : 0.0f;
    float e = expf(-norm);
    float dd = e - mean;
    float smear = cutoff * expf(-beta * dd * dd);

    float s_over = smear / ns;

    int base = tid * 3;
    g_P[base + 0] = s_over * d0;
    g_P[base + 1] = s_over * d1;
    g_P[base + 2] = s_over * d2;
}

// ---------------------------------------------------------------------------
// Kernel 2: stream W once. One block per (a,b,d) -> contiguous 64 KB slice
// over (e,k,h). Stream loop issues 4 independent LDG.128 per batch to build
// memory-level parallelism (512 B in flight per warp).
// ---------------------------------------------------------------------------
__global__ void __launch_bounds__(256) k2_main(const float* __restrict__ W) {
    __shared__ float4 scoef[256];          // [j = e*16+k] -> (z0,z1,z2,z3), 4 KB
    __shared__ float  sred[8 * 256];       // [warp][z*64+h], 8 KB

    int blk = blockIdx.x;                  // a*256 + b*16 + d
    int d = blk & 15;
    int b = (blk >> 4) & 15;
    int a = blk >> 8;

    int t = threadIdx.x;

    // --- coefficient table: thread t computes j = t ---
    {
        int e = t >> 4;
        int k = t & 15;
        float cf[4];
#pragma unroll
        for (int z = 0; z < 4; z++) {
            const float* p1 = &g_P[((((z * NN + a) * NN + b) * NK) + k) * 3];
            const float* p2 = &g_P[((((z * NN + d) * NN + e) * NK) + k) * 3];
            cf[z] = p1[0] * p2[0] + p1[1] * p2[1] + p1[2] * p2[2];
        }
        scoef[t] = make_float4(cf[0], cf[1], cf[2], cf[3]);
    }
    __syncthreads();

    // --- main streaming loop: 16 j-rows per thread-group, batched 4 deep ---
    int h4 = t & 15;                       // which float4 of the 64 h values
    int g  = t >> 4;                       // group 0..15 over j-rows
    const float4* Wp = (const float4*)W + ((size_t)blk << 12) + (g * 16 + h4);

    float acc0x = 0.f, acc0y = 0.f, acc0z = 0.f, acc0w = 0.f;
    float acc1x = 0.f, acc1y = 0.f, acc1z = 0.f, acc1w = 0.f;
    float acc2x = 0.f, acc2y = 0.f, acc2z = 0.f, acc2w = 0.f;
    float acc3x = 0.f, acc3y = 0.f, acc3z = 0.f, acc3w = 0.f;

#pragma unroll
    for (int it = 0; it < 16; it += 4) {
        // 4 independent streaming loads, back-to-back (rows it*16+g .. +3*16+g)
        float4 w0 = __ldcs(Wp + (size_t)(it + 0) * 256);
        float4 w1 = __ldcs(Wp + (size_t)(it + 1) * 256);
        float4 w2 = __ldcs(Wp + (size_t)(it + 2) * 256);
        float4 w3 = __ldcs(Wp + (size_t)(it + 3) * 256);

        float4 c0 = scoef[g + (it + 0) * 16];
        float4 c1 = scoef[g + (it + 1) * 16];
        float4 c2 = scoef[g + (it + 2) * 16];
        float4 c3 = scoef[g + (it + 3) * 16];

        acc0x += c0.x * w0.x; acc0y += c0.x * w0.y; acc0z += c0.x * w0.z; acc0w += c0.x * w0.w;
        acc1x += c0.y * w0.x; acc1y += c0.y * w0.y; acc1z += c0.y * w0.z; acc1w += c0.y * w0.w;
        acc2x += c0.z * w0.x; acc2y += c0.z * w0.y; acc2z += c0.z * w0.z; acc2w += c0.z * w0.w;
        acc3x += c0.w * w0.x; acc3y += c0.w * w0.y; acc3z += c0.w * w0.z; acc3w += c0.w * w0.w;

        acc0x += c1.x * w1.x; acc0y += c1.x * w1.y; acc0z += c1.x * w1.z; acc0w += c1.x * w1.w;
        acc1x += c1.y * w1.x; acc1y += c1.y * w1.y; acc1z += c1.y * w1.z; acc1w += c1.y * w1.w;
        acc2x += c1.z * w1.x; acc2y += c1.z * w1.y; acc2z += c1.z * w1.z; acc2w += c1.z * w1.w;
        acc3x += c1.w * w1.x; acc3y += c1.w * w1.y; acc3z += c1.w * w1.z; acc3w += c1.w * w1.w;

        acc0x += c2.x * w2.x; acc0y += c2.x * w2.y; acc0z += c2.x * w2.z; acc0w += c2.x * w2.w;
        acc1x += c2.y * w2.x; acc1y += c2.y * w2.y; acc1z += c2.y * w2.z; acc1w += c2.y * w2.w;
        acc2x += c2.z * w2.x; acc2y += c2.z * w2.y; acc2z += c2.z * w2.z; acc2w += c2.z * w2.w;
        acc3x += c2.w * w2.x; acc3y += c2.w * w2.y; acc3z += c2.w * w2.z; acc3w += c2.w * w2.w;

        acc0x += c3.x * w3.x; acc0y += c3.x * w3.y; acc0z += c3.x * w3.z; acc0w += c3.x * w3.w;
        acc1x += c3.y * w3.x; acc1y += c3.y * w3.y; acc1z += c3.y * w3.z; acc1w += c3.y * w3.w;
        acc2x += c3.z * w3.x; acc2y += c3.z * w3.y; acc2z += c3.z * w3.z; acc2w += c3.z * w3.w;
        acc3x += c3.w * w3.x; acc3y += c3.w * w3.y; acc3z += c3.w * w3.z; acc3w += c3.w * w3.w;
    }

    // --- warp-level pre-reduction: combine g pairs (lane l with l^16, same h4) ---
#define SHFL_ADD(v) v += __shfl_xor_sync(0xFFFFFFFFu, v, 16)
    SHFL_ADD(acc0x); SHFL_ADD(acc0y); SHFL_ADD(acc0z); SHFL_ADD(acc0w);
    SHFL_ADD(acc1x); SHFL_ADD(acc1y); SHFL_ADD(acc1z); SHFL_ADD(acc1w);
    SHFL_ADD(acc2x); SHFL_ADD(acc2y); SHFL_ADD(acc2z); SHFL_ADD(acc2w);
    SHFL_ADD(acc3x); SHFL_ADD(acc3y); SHFL_ADD(acc3z); SHFL_ADD(acc3w);
#undef SHFL_ADD

    int lane = t & 31;
    int wrp  = t >> 5;                     // 0..7
    if (lane < 16) {
        float4* r4 = (float4*)sred;        // [8 warps][4 z][16 h4] of float4
        int base = (wrp * 4) * 16 + h4;
        r4[base + 0 * 16] = make_float4(acc0x, acc0y, acc0z, acc0w);
        r4[base + 1 * 16] = make_float4(acc1x, acc1y, acc1z, acc1w);
        r4[base + 2 * 16] = make_float4(acc2x, acc2y, acc2z, acc2w);
        r4[base + 3 * 16] = make_float4(acc3x, acc3y, acc3z, acc3w);
    }
    __syncthreads();

    // thread t owns (z = t>>6, h = t&63); sum across 8 warps, one atomic.
    float s = 0.0f;
#pragma unroll
    for (int w2 = 0; w2 < 8; w2++) s += sred[w2 * 256 + t];

    int z = t >> 6;
    int h = t & 63;
    atomicAdd(&g_h[(z * NN + a) * NH + h], s);
}

// ---------------------------------------------------------------------------
// Kernel 3: out[z,a] = silu(h[z,a,:]) . w_fc + b_fc
// ---------------------------------------------------------------------------
__global__ void k3_head(const float* __restrict__ w_fc,
                        const float* __restrict__ b_fc,
                        float* __restrict__ out) {
    int t = threadIdx.x;                   // 0..63 = z*16+a
    if (t >= ZB * NN) return;
    const float* hp = &g_h[t * NH];
    float acc = 0.0f;
#pragma unroll
    for (int h = 0; h < NH; h++) {
        float v = hp[h];
        float s = v / (1.0f + expf(-v));
        acc += s * w_fc[h];
    }
    out[t] = acc + b_fc[0];
}

// ---------------------------------------------------------------------------
extern "C" void kernel_launch(void* const* d_in, const int* in_sizes, int n_in,
                              void* d_out, int out_size) {
    const float* x   = nullptr;
    const float* W   = nullptr;
    const float* wfc = nullptr;
    const float* bfc = nullptr;
    for (int i = 0; i < n_in; i++) {
        long long s = in_sizes[i];
        if      (s == (long long)ZB * NN * 3)                 x   = (const float*)d_in[i];
        else if (s == (long long)NN * NN * NN * NN * NK * NH) W   = (const float*)d_in[i];
        else if (s == NH)                                     wfc = (const float*)d_in[i];
        else if (s == 1)                                      bfc = (const float*)d_in[i];
    }

    k1_basis<<<64, 256>>>(x);
    k2_main<<<NN * NN * NN, 256>>>(W);   // 4096 blocks, 64 KB each
    k3_head<<<1, 64>>>(wfc, bfc, (float*)d_out);
}

// round 4
// speedup vs baseline: 1.1101x; 1.0109x over previous
#include <cuda_runtime.h>
#include <math.h>

// Problem constants: B=4, N=16, K=16, H=64, O=1
#define ZB 4
#define NN 16
#define NK 16
#define NH 64

// Scratch (allocation-free rule: __device__ globals)
__device__ float g_P[ZB * NN * NN * NK * 3];   // basis, 192 KB (L2-resident)
__device__ float g_h[ZB * NN * NH];            // h accumulator, 16 KB

// ---------------------------------------------------------------------------
// Kernel 1: compute basis P and zero the h accumulator.
// ---------------------------------------------------------------------------
__global__ void k1_basis(const float* __restrict__ x) {
    int tid = blockIdx.x * blockDim.x + threadIdx.x;

    if (tid < ZB * NN * NH) g_h[tid] = 0.0f;

    if (tid >= ZB * NN * NN * NK) return;

    int k = tid & 15;
    int j = (tid >> 4) & 15;
    int i = (tid >> 8) & 15;
    int z = tid >> 12;

    const float* xi = x + (z * NN + i) * 3;
    const float* xj = x + (z * NN + j) * 3;
    float d0 = xi[0] - xj[0];
    float d1 = xi[1] - xj[1];
    float d2 = xi[2] - xj[2];

    float ns = d0 * d0 + d1 * d1 + d2 * d2 + 1e-5f;
    float norm = sqrtf(ns);

    const float start = expf(-5.0f);
    float mean = start + (float)k * (1.0f - start) * (1.0f / 15.0f);
    float bden = 0.125f * (1.0f - start);
    float beta = 1.0f / (bden * bden);

    float cutoff = (norm < 5.0f)
                 ? 0.5f * (cospif(norm * 0.2f) + 1.0f)
                 : 0.0f;
    float e = expf(-norm);
    float dd = e - mean;
    float smear = cutoff * expf(-beta * dd * dd);

    float s_over = smear / ns;

    int base = tid * 3;
    g_P[base + 0] = s_over * d0;
    g_P[base + 1] = s_over * d1;
    g_P[base + 2] = s_over * d2;
}

// ---------------------------------------------------------------------------
// Kernel 2: stream W once, single-wave persistent-style grid.
// 512 blocks = 16 a-groups x 32 sub-blocks. Block (a,sub) streams 8 slices
// (b,d) = sub + s*32, s=0..7 (512 KB), carrying fp32 accumulators across
// slices; one epilogue + one atomic per thread at the end.
// ---------------------------------------------------------------------------
__global__ void __launch_bounds__(256, 4) k2_main(const float* __restrict__ W) {
    __shared__ float4 scoef[256];          // [j = e*16+k] -> (z0,z1,z2,z3), 4 KB
    __shared__ float  sred[8 * 256];       // [warp][z*64+h], 8 KB

    int a   = blockIdx.x >> 5;             // 0..15
    int sub = blockIdx.x & 31;             // 0..31

    int t  = threadIdx.x;
    int h4 = t & 15;                       // which float4 of the 64 h values
    int g  = t >> 4;                       // group 0..15 over j-rows

    float acc0x = 0.f, acc0y = 0.f, acc0z = 0.f, acc0w = 0.f;
    float acc1x = 0.f, acc1y = 0.f, acc1z = 0.f, acc1w = 0.f;
    float acc2x = 0.f, acc2y = 0.f, acc2z = 0.f, acc2w = 0.f;
    float acc3x = 0.f, acc3y = 0.f, acc3z = 0.f, acc3w = 0.f;

    for (int s = 0; s < 8; s++) {
        int slice = sub + (s << 5);        // 0..255 within this a-group
        int b = slice >> 4;
        int d = slice & 15;

        // --- coefficient table: thread t computes j = t ---
        {
            int e = t >> 4;
            int k = t & 15;
            float cf[4];
#pragma unroll
            for (int z = 0; z < 4; z++) {
                const float* p1 = &g_P[((((z * NN + a) * NN + b) * NK) + k) * 3];
                const float* p2 = &g_P[((((z * NN + d) * NN + e) * NK) + k) * 3];
                cf[z] = p1[0] * p2[0] + p1[1] * p2[1] + p1[2] * p2[2];
            }
            scoef[t] = make_float4(cf[0], cf[1], cf[2], cf[3]);
        }
        __syncthreads();

        // --- stream this 64 KB slice: 16 rows per thread, loads batched 4 deep ---
        const float4* Wp = (const float4*)W
                         + (((size_t)a * 256 + slice) << 12) + (g * 16 + h4);

#pragma unroll
        for (int it = 0; it < 16; it += 4) {
            // 4 independent streaming loads back-to-back (MLP)
            float4 w0 = __ldcs(Wp + (size_t)(it + 0) * 256);
            float4 w1 = __ldcs(Wp + (size_t)(it + 1) * 256);
            float4 w2 = __ldcs(Wp + (size_t)(it + 2) * 256);
            float4 w3 = __ldcs(Wp + (size_t)(it + 3) * 256);

            // consume one at a time (keeps live registers low)
            float4 c;
            c = scoef[g + (it + 0) * 16];
            acc0x += c.x * w0.x; acc0y += c.x * w0.y; acc0z += c.x * w0.z; acc0w += c.x * w0.w;
            acc1x += c.y * w0.x; acc1y += c.y * w0.y; acc1z += c.y * w0.z; acc1w += c.y * w0.w;
            acc2x += c.z * w0.x; acc2y += c.z * w0.y; acc2z += c.z * w0.z; acc2w += c.z * w0.w;
            acc3x += c.w * w0.x; acc3y += c.w * w0.y; acc3z += c.w * w0.z; acc3w += c.w * w0.w;

            c = scoef[g + (it + 1) * 16];
            acc0x += c.x * w1.x; acc0y += c.x * w1.y; acc0z += c.x * w1.z; acc0w += c.x * w1.w;
            acc1x += c.y * w1.x; acc1y += c.y * w1.y; acc1z += c.y * w1.z; acc1w += c.y * w1.w;
            acc2x += c.z * w1.x; acc2y += c.z * w1.y; acc2z += c.z * w1.z; acc2w += c.z * w1.w;
            acc3x += c.w * w1.x; acc3y += c.w * w1.y; acc3z += c.w * w1.z; acc3w += c.w * w1.w;

            c = scoef[g + (it + 2) * 16];
            acc0x += c.x * w2.x; acc0y += c.x * w2.y; acc0z += c.x * w2.z; acc0w += c.x * w2.w;
            acc1x += c.y * w2.x; acc1y += c.y * w2.y; acc1z += c.y * w2.z; acc1w += c.y * w2.w;
            acc2x += c.z * w2.x; acc2y += c.z * w2.y; acc2z += c.z * w2.z; acc2w += c.z * w2.w;
            acc3x += c.w * w2.x; acc3y += c.w * w2.y; acc3z += c.w * w2.z; acc3w += c.w * w2.w;

            c = scoef[g + (it + 3) * 16];
            acc0x += c.x * w3.x; acc0y += c.x * w3.y; acc0z += c.x * w3.z; acc0w += c.x * w3.w;
            acc1x += c.y * w3.x; acc1y += c.y * w3.y; acc1z += c.y * w3.z; acc1w += c.y * w3.w;
            acc2x += c.z * w3.x; acc2y += c.z * w3.y; acc2z += c.z * w3.z; acc2w += c.z * w3.w;
            acc3x += c.w * w3.x; acc3y += c.w * w3.y; acc3z += c.w * w3.z; acc3w += c.w * w3.w;
        }
        __syncthreads();                   // all warps done reading scoef before rewrite
    }

    // --- warp-level pre-reduction: combine g pairs (lane l with l^16, same h4) ---
#define SHFL_ADD(v) v += __shfl_xor_sync(0xFFFFFFFFu, v, 16)
    SHFL_ADD(acc0x); SHFL_ADD(acc0y); SHFL_ADD(acc0z); SHFL_ADD(acc0w);
    SHFL_ADD(acc1x); SHFL_ADD(acc1y); SHFL_ADD(acc1z); SHFL_ADD(acc1w);
    SHFL_ADD(acc2x); SHFL_ADD(acc2y); SHFL_ADD(acc2z); SHFL_ADD(acc2w);
    SHFL_ADD(acc3x); SHFL_ADD(acc3y); SHFL_ADD(acc3z); SHFL_ADD(acc3w);
#undef SHFL_ADD

    int lane = t & 31;
    int wrp  = t >> 5;                     // 0..7
    if (lane < 16) {
        float4* r4 = (float4*)sred;        // [8 warps][4 z][16 h4] of float4
        int base = (wrp * 4) * 16 + h4;
        r4[base + 0 * 16] = make_float4(acc0x, acc0y, acc0z, acc0w);
        r4[base + 1 * 16] = make_float4(acc1x, acc1y, acc1z, acc1w);
        r4[base + 2 * 16] = make_float4(acc2x, acc2y, acc2z, acc2w);
        r4[base + 3 * 16] = make_float4(acc3x, acc3y, acc3z, acc3w);
    }
    __syncthreads();

    // thread t owns (z = t>>6, h = t&63); sum across 8 warps, one atomic.
    float sum = 0.0f;
#pragma unroll
    for (int w2 = 0; w2 < 8; w2++) sum += sred[w2 * 256 + t];

    int z = t >> 6;
    int h = t & 63;
    atomicAdd(&g_h[(z * NN + a) * NH + h], sum);
}

// ---------------------------------------------------------------------------
// Kernel 3: out[z,a] = silu(h[z,a,:]) . w_fc + b_fc
// ---------------------------------------------------------------------------
__global__ void k3_head(const float* __restrict__ w_fc,
                        const float* __restrict__ b_fc,
                        float* __restrict__ out) {
    int t = threadIdx.x;                   // 0..63 = z*16+a
    if (t >= ZB * NN) return;
    const float* hp = &g_h[t * NH];
    float acc = 0.0f;
#pragma unroll
    for (int h = 0; h < NH; h++) {
        float v = hp[h];
        float s = v / (1.0f + expf(-v));
        acc += s * w_fc[h];
    }
    out[t] = acc + b_fc[0];
}

// ---------------------------------------------------------------------------
extern "C" void kernel_launch(void* const* d_in, const int* in_sizes, int n_in,
                              void* d_out, int out_size) {
    const float* x   = nullptr;
    const float* W   = nullptr;
    const float* wfc = nullptr;
    const float* bfc = nullptr;
    for (int i = 0; i < n_in; i++) {
        long long s = in_sizes[i];
        if      (s == (long long)ZB * NN * 3)                 x   = (const float*)d_in[i];
        else if (s == (long long)NN * NN * NN * NN * NK * NH) W   = (const float*)d_in[i];
        else if (s == NH)                                     wfc = (const float*)d_in[i];
        else if (s == 1)                                      bfc = (const float*)d_in[i];
    }

    k1_basis<<<64, 256>>>(x);
    k2_main<<<512, 256>>>(W);   // 16 a-groups x 32 blocks, 512 KB per block
    k3_head<<<1, 64>>>(wfc, bfc, (float*)d_out);
}

// round 5
// speedup vs baseline: 1.3849x; 1.2475x over previous
#include <cuda_runtime.h>
#include <math.h>

// Problem constants: B=4, N=16, K=16, H=64, O=1
#define ZB 4
#define NN 16
#define NK 16
#define NH 64

// Per-block partials: [a(16)][sub(32)][z*64+h(256)] = 128K floats = 512 KB.
// Fully overwritten by k2 each call -> no init needed, no atomics.
__device__ float g_part[16 * 32 * 256];

// ---------------------------------------------------------------------------
// Inline basis eval: P[z,i,j,k,:] = cutoff*exp(-beta*(exp(-norm)-mean_k)^2)
//                                   * diff / norm_sq
// ---------------------------------------------------------------------------
__device__ __forceinline__ float3 smear_vec(const float* __restrict__ xi,
                                            const float* __restrict__ xj,
                                            int k) {
    float d0 = xi[0] - xj[0];
    float d1 = xi[1] - xj[1];
    float d2 = xi[2] - xj[2];

    float ns = d0 * d0 + d1 * d1 + d2 * d2 + 1e-5f;
    float norm = sqrtf(ns);

    const float start = expf(-5.0f);                 // literal, const-folded
    float mean = start + (float)k * (1.0f - start) * (1.0f / 15.0f);
    float bden = 0.125f * (1.0f - start);
    float beta = 1.0f / (bden * bden);

    float cutoff = (norm < 5.0f)
                 ? 0.5f * (cospif(norm * 0.2f) + 1.0f)
                 : 0.0f;
    float e = expf(-norm);
    float dd = e - mean;
    float smear = cutoff * expf(-beta * dd * dd);
    float so = smear / ns;
    return make_float3(so * d0, so * d1, so * d2);
}

// ---------------------------------------------------------------------------
// Kernel 2: single-wave grid, 512 blocks = 16 a-groups x 32 sub-blocks.
// Block (a,sub) streams 8 slices (b,d) = sub + s*32 (d fixed = sub&15),
// 512 KB of W, with ALL coefficient tables precomputed -> barrier-free
// mainloop. One coalesced partial store per block, no atomics.
// ---------------------------------------------------------------------------
__global__ void __launch_bounds__(256, 4) k2_main(const float* __restrict__ W,
                                                  const float* __restrict__ x) {
    __shared__ float  sx[ZB * NN * 3];         // coords, 768 B
    __shared__ float  sAux[8 * 256];           // 8 KB: sP1 first, sred later
    __shared__ float4 scoef[8 * 256];          // 32 KB: [s][j=e*16+k] -> (z0..z3)

    int a   = blockIdx.x >> 5;                 // 0..15
    int sub = blockIdx.x & 31;                 // 0..31
    int d   = sub & 15;                        // fixed across slices

    int t  = threadIdx.x;
    int h4 = t & 15;                           // float4 index within 64 h
    int g  = t >> 4;                           // j-row group 0..15

    // --- load coords ---
    if (t < ZB * NN * 3) sx[t] = x[t];
    __syncthreads();

    // --- cooperative P1[s][k][z] = P[z,a,b_s,k,:], 512 evals, 2 per thread ---
    for (int i = t; i < 512; i += 256) {
        int s = i >> 6;                        // 0..7
        int k = (i >> 2) & 15;
        int z = i & 3;
        int b = (sub >> 4) + (s << 1);         // b_s = slice>>4
        float3 v = smear_vec(&sx[(z * NN + a) * 3], &sx[(z * NN + b) * 3], k);
        float* p = &sAux[i * 3];
        p[0] = v.x; p[1] = v.y; p[2] = v.z;
    }
    __syncthreads();

    // --- per-thread P2[z] = P[z,d,e,k,:] and all 8 coef tables ---
    {
        int e = t >> 4;
        int k = t & 15;
        float3 p2[4];
#pragma unroll
        for (int z = 0; z < 4; z++)
            p2[z] = smear_vec(&sx[(z * NN + d) * 3], &sx[(z * NN + e) * 3], k);

#pragma unroll
        for (int s = 0; s < 8; s++) {
            float cf[4];
#pragma unroll
            for (int z = 0; z < 4; z++) {
                const float* p1 = &sAux[((s * 16 + k) * 4 + z) * 3];
                cf[z] = p1[0] * p2[z].x + p1[1] * p2[z].y + p1[2] * p2[z].z;
            }
            scoef[s * 256 + t] = make_float4(cf[0], cf[1], cf[2], cf[3]);
        }
    }
    __syncthreads();                           // coef tables ready; last sync

    // --- barrier-free stream: 8 slices x 64 KB ---
    const float4* Wbase = (const float4*)W
                        + (((size_t)a * 256 + sub) << 12) + (g * 16 + h4);

    float acc0x = 0.f, acc0y = 0.f, acc0z = 0.f, acc0w = 0.f;
    float acc1x = 0.f, acc1y = 0.f, acc1z = 0.f, acc1w = 0.f;
    float acc2x = 0.f, acc2y = 0.f, acc2z = 0.f, acc2w = 0.f;
    float acc3x = 0.f, acc3y = 0.f, acc3z = 0.f, acc3w = 0.f;

#pragma unroll 1
    for (int s = 0; s < 8; s++) {
        const float4* Wp = Wbase + ((size_t)s << 17);   // +32 slices * 4096 float4
        const float4* cp = scoef + s * 256;

#pragma unroll
        for (int it = 0; it < 16; it += 4) {
            float4 w0 = __ldcs(Wp + (size_t)(it + 0) * 256);
            float4 w1 = __ldcs(Wp + (size_t)(it + 1) * 256);
            float4 w2 = __ldcs(Wp + (size_t)(it + 2) * 256);
            float4 w3 = __ldcs(Wp + (size_t)(it + 3) * 256);

            float4 c;
            c = cp[g + (it + 0) * 16];
            acc0x += c.x * w0.x; acc0y += c.x * w0.y; acc0z += c.x * w0.z; acc0w += c.x * w0.w;
            acc1x += c.y * w0.x; acc1y += c.y * w0.y; acc1z += c.y * w0.z; acc1w += c.y * w0.w;
            acc2x += c.z * w0.x; acc2y += c.z * w0.y; acc2z += c.z * w0.z; acc2w += c.z * w0.w;
            acc3x += c.w * w0.x; acc3y += c.w * w0.y; acc3z += c.w * w0.z; acc3w += c.w * w0.w;

            c = cp[g + (it + 1) * 16];
            acc0x += c.x * w1.x; acc0y += c.x * w1.y; acc0z += c.x * w1.z; acc0w += c.x * w1.w;
            acc1x += c.y * w1.x; acc1y += c.y * w1.y; acc1z += c.y * w1.z; acc1w += c.y * w1.w;
            acc2x += c.z * w1.x; acc2y += c.z * w1.y; acc2z += c.z * w1.z; acc2w += c.z * w1.w;
            acc3x += c.w * w1.x; acc3y += c.w * w1.y; acc3z += c.w * w1.z; acc3w += c.w * w1.w;

            c = cp[g + (it + 2) * 16];
            acc0x += c.x * w2.x; acc0y += c.x * w2.y; acc0z += c.x * w2.z; acc0w += c.x * w2.w;
            acc1x += c.y * w2.x; acc1y += c.y * w2.y; acc1z += c.y * w2.z; acc1w += c.y * w2.w;
            acc2x += c.z * w2.x; acc2y += c.z * w2.y; acc2z += c.z * w2.z; acc2w += c.z * w2.w;
            acc3x += c.w * w2.x; acc3y += c.w * w2.y; acc3z += c.w * w2.z; acc3w += c.w * w2.w;

            c = cp[g + (it + 3) * 16];
            acc0x += c.x * w3.x; acc0y += c.x * w3.y; acc0z += c.x * w3.z; acc0w += c.x * w3.w;
            acc1x += c.y * w3.x; acc1y += c.y * w3.y; acc1z += c.y * w3.z; acc1w += c.y * w3.w;
            acc2x += c.z * w3.x; acc2y += c.z * w3.y; acc2z += c.z * w3.z; acc2w += c.z * w3.w;
            acc3x += c.w * w3.x; acc3y += c.w * w3.y; acc3z += c.w * w3.z; acc3w += c.w * w3.w;
        }
    }

    // --- epilogue: shfl-combine g pairs, 8-warp smem reduce, one STG ---
#define SHFL_ADD(v) v += __shfl_xor_sync(0xFFFFFFFFu, v, 16)
    SHFL_ADD(acc0x); SHFL_ADD(acc0y); SHFL_ADD(acc0z); SHFL_ADD(acc0w);
    SHFL_ADD(acc1x); SHFL_ADD(acc1y); SHFL_ADD(acc1z); SHFL_ADD(acc1w);
    SHFL_ADD(acc2x); SHFL_ADD(acc2y); SHFL_ADD(acc2z); SHFL_ADD(acc2w);
    SHFL_ADD(acc3x); SHFL_ADD(acc3y); SHFL_ADD(acc3z); SHFL_ADD(acc3w);
#undef SHFL_ADD

    // sAux reuse as sred is safe: its last reads happened before the
    // coef-table __syncthreads above.
    int lane = t & 31;
    int wrp  = t >> 5;                         // 0..7
    if (lane < 16) {
        float4* r4 = (float4*)sAux;            // [8 warps][4 z][16 h4] of float4
        int base = (wrp * 4) * 16 + h4;
        r4[base + 0 * 16] = make_float4(acc0x, acc0y, acc0z, acc0w);
        r4[base + 1 * 16] = make_float4(acc1x, acc1y, acc1z, acc1w);
        r4[base + 2 * 16] = make_float4(acc2x, acc2y, acc2z, acc2w);
        r4[base + 3 * 16] = make_float4(acc3x, acc3y, acc3z, acc3w);
    }
    __syncthreads();

    float sum = 0.0f;
#pragma unroll
    for (int w2 = 0; w2 < 8; w2++) sum += sAux[w2 * 256 + t];

    g_part[blockIdx.x * 256 + t] = sum;        // coalesced, no atomic
}

// ---------------------------------------------------------------------------
// Kernel 3: reduce partials over sub, silu, dot with w_fc.
// Grid 64 blocks (z,a), 64 threads (h).
// ---------------------------------------------------------------------------
__global__ void k3_head(const float* __restrict__ w_fc,
                        const float* __restrict__ b_fc,
                        float* __restrict__ out) {
    __shared__ float swarp[2];
    int z = blockIdx.x >> 4;
    int a = blockIdx.x & 15;
    int h = threadIdx.x;                       // 0..63

    const float* p = &g_part[(a * 32) * 256 + z * 64 + h];
    float v = 0.0f;
#pragma unroll
    for (int sub = 0; sub < 32; sub++) v += p[sub * 256];

    float s = (v / (1.0f + expf(-v))) * w_fc[h];

    // reduce 64 -> 1
#pragma unroll
    for (int o = 16; o > 0; o >>= 1) s += __shfl_xor_sync(0xFFFFFFFFu, s, o);
    if ((h & 31) == 0) swarp[h >> 5] = s;
    __syncthreads();
    if (h == 0) out[z * NN + a] = swarp[0] + swarp[1] + b_fc[0];
}

// ---------------------------------------------------------------------------
extern "C" void kernel_launch(void* const* d_in, const int* in_sizes, int n_in,
                              void* d_out, int out_size) {
    const float* x   = nullptr;
    const float* W   = nullptr;
    const float* wfc = nullptr;
    const float* bfc = nullptr;
    for (int i = 0; i < n_in; i++) {
        long long s = in_sizes[i];
        if      (s == (long long)ZB * NN * 3)                 x   = (const float*)d_in[i];
        else if (s == (long long)NN * NN * NN * NN * NK * NH) W   = (const float*)d_in[i];
        else if (s == NH)                                     wfc = (const float*)d_in[i];
        else if (s == 1)                                      bfc = (const float*)d_in[i];
    }

    k2_main<<<512, 256>>>(W, x);   // single wave, 512 KB per block
    k3_head<<<64, 64>>>(wfc, bfc, (float*)d_out);
}